// round 1
// baseline (speedup 1.0000x reference)
#include <cuda_runtime.h>

#define NGMAX 8192
#define DCOLS 128
__device__ float g_Z[NGMAX];

__global__ void zero_kernel(float* out, int n_out, int ng) {
    int i = blockIdx.x * blockDim.x + threadIdx.x;
    if (i < n_out) out[i] = 0.0f;
    if (i < ng)    g_Z[i] = 0.0f;
}

// One warp per chunk of rows_per_warp contiguous rows.
// Lane k holds columns [4k, 4k+4) as a float4.
__global__ void agg_kernel(const float* __restrict__ H,
                           const int*   __restrict__ batch,
                           const float* __restrict__ w,
                           const float* __restrict__ b,
                           float* __restrict__ out,
                           int V, int rows_per_warp) {
    int warp = (blockIdx.x * blockDim.x + threadIdx.x) >> 5;
    int lane = threadIdx.x & 31;

    long start = (long)warp * rows_per_warp;
    if (start >= V) return;
    long end = start + rows_per_warp;
    if (end > V) end = V;

    float4 w4 = reinterpret_cast<const float4*>(w)[lane];
    float bias = b[0];

    float4 acc = make_float4(0.f, 0.f, 0.f, 0.f);
    float  zacc = 0.f;
    int    seg  = batch[start];

    for (long r = start; r < end; ++r) {
        int s = batch[r];
        float4 h = reinterpret_cast<const float4*>(H + r * DCOLS)[lane];
        float p = h.x * w4.x + h.y * w4.y + h.z * w4.z + h.w * w4.w;
        p += __shfl_xor_sync(0xFFFFFFFFu, p, 16);
        p += __shfl_xor_sync(0xFFFFFFFFu, p, 8);
        p += __shfl_xor_sync(0xFFFFFFFFu, p, 4);
        p += __shfl_xor_sync(0xFFFFFFFFu, p, 2);
        p += __shfl_xor_sync(0xFFFFFFFFu, p, 1);
        float l = __expf(p + bias);

        if (s != seg) {
            float* o = out + (long)seg * DCOLS + lane * 4;
            atomicAdd(o + 0, acc.x);
            atomicAdd(o + 1, acc.y);
            atomicAdd(o + 2, acc.z);
            atomicAdd(o + 3, acc.w);
            if (lane == 0) atomicAdd(&g_Z[seg], zacc);
            acc = make_float4(0.f, 0.f, 0.f, 0.f);
            zacc = 0.f;
            seg = s;
        }

        acc.x += l * h.x;
        acc.y += l * h.y;
        acc.z += l * h.z;
        acc.w += l * h.w;
        zacc  += l;
    }

    // final flush
    float* o = out + (long)seg * DCOLS + lane * 4;
    atomicAdd(o + 0, acc.x);
    atomicAdd(o + 1, acc.y);
    atomicAdd(o + 2, acc.z);
    atomicAdd(o + 3, acc.w);
    if (lane == 0) atomicAdd(&g_Z[seg], zacc);
}

__global__ void div_kernel(float* out, int n_out) {
    int i = blockIdx.x * blockDim.x + threadIdx.x;
    if (i < n_out) {
        float z = g_Z[i >> 7];  // i / 128 -> graph id
        out[i] = (z > 0.f) ? out[i] / z : 0.f;
    }
}

extern "C" void kernel_launch(void* const* d_in, const int* in_sizes, int n_in,
                              void* d_out, int out_size) {
    const float* H     = (const float*)d_in[0];
    const int*   batch = (const int*)d_in[1];
    const float* w     = (const float*)d_in[2];
    const float* b     = (const float*)d_in[3];
    float*       out   = (float*)d_out;

    int V  = in_sizes[1];           // number of rows
    int ng = out_size / DCOLS;      // number of graphs

    // 1) zero output + Z scratch
    {
        int n = out_size > ng ? out_size : ng;
        int threads = 256;
        int blocks = (n + threads - 1) / threads;
        zero_kernel<<<blocks, threads>>>(out, out_size, ng);
    }

    // 2) single-pass fused numerator + Z
    {
        const int rows_per_warp = 128;
        long warps = ((long)V + rows_per_warp - 1) / rows_per_warp;
        int threads = 256;
        long blocks = (warps * 32 + threads - 1) / threads;
        agg_kernel<<<(int)blocks, threads>>>(H, batch, w, b, out, V, rows_per_warp);
    }

    // 3) divide by Z
    {
        int threads = 256;
        int blocks = (out_size + threads - 1) / threads;
        div_kernel<<<blocks, threads>>>(out, out_size);
    }
}

// round 3
// speedup vs baseline: 1.7109x; 1.7109x over previous
#include <cuda_runtime.h>

#define NGMAX 8192
#define DCOLS 128
__device__ float g_Z[NGMAX];

__global__ void zero_kernel(float* out, int n_out, int ng) {
    int i = blockIdx.x * blockDim.x + threadIdx.x;
    if (i < n_out) out[i] = 0.0f;
    if (i < ng)    g_Z[i] = 0.0f;
}

__device__ __forceinline__ float warp_bcast_sum(float p) {
    p += __shfl_xor_sync(0xFFFFFFFFu, p, 16);
    p += __shfl_xor_sync(0xFFFFFFFFu, p, 8);
    p += __shfl_xor_sync(0xFFFFFFFFu, p, 4);
    p += __shfl_xor_sync(0xFFFFFFFFu, p, 2);
    p += __shfl_xor_sync(0xFFFFFFFFu, p, 1);
    return p;
}

// One warp per chunk of rows_per_warp contiguous rows.
// Lane k holds columns [4k, 4k+4) as a float4. 4-row software pipeline.
__global__ void agg_kernel(const float* __restrict__ H,
                           const int*   __restrict__ batch,
                           const float* __restrict__ w,
                           const float* __restrict__ b,
                           float* __restrict__ out,
                           int V, int rows_per_warp) {
    int warp = (blockIdx.x * blockDim.x + threadIdx.x) >> 5;
    int lane = threadIdx.x & 31;

    long start = (long)warp * rows_per_warp;
    if (start >= V) return;
    long end = start + rows_per_warp;
    if (end > V) end = V;

    float4 w4 = reinterpret_cast<const float4*>(w)[lane];
    float bias = b[0];

    float4 acc = make_float4(0.f, 0.f, 0.f, 0.f);
    float  zacc = 0.f;
    int    seg  = batch[start];

#define FLUSH()                                                         \
    do {                                                                \
        float* o = out + (long)seg * DCOLS + lane * 4;                  \
        atomicAdd(o + 0, acc.x);                                        \
        atomicAdd(o + 1, acc.y);                                        \
        atomicAdd(o + 2, acc.z);                                        \
        atomicAdd(o + 3, acc.w);                                        \
        if (lane == 0) atomicAdd(&g_Z[seg], zacc);                      \
        acc = make_float4(0.f, 0.f, 0.f, 0.f);                          \
        zacc = 0.f;                                                     \
    } while (0)

#define ACCUM(s_, h_, l_)                                               \
    do {                                                                \
        if ((s_) != seg) { FLUSH(); seg = (s_); }                       \
        acc.x += (l_) * (h_).x;                                         \
        acc.y += (l_) * (h_).y;                                         \
        acc.z += (l_) * (h_).z;                                         \
        acc.w += (l_) * (h_).w;                                         \
        zacc  += (l_);                                                  \
    } while (0)

    long r = start;
    for (; r + 4 <= end; r += 4) {
        // front-batched independent loads (MLP)
        int4   bv = *reinterpret_cast<const int4*>(batch + r);
        float4 h0 = reinterpret_cast<const float4*>(H + (r + 0) * DCOLS)[lane];
        float4 h1 = reinterpret_cast<const float4*>(H + (r + 1) * DCOLS)[lane];
        float4 h2 = reinterpret_cast<const float4*>(H + (r + 2) * DCOLS)[lane];
        float4 h3 = reinterpret_cast<const float4*>(H + (r + 3) * DCOLS)[lane];

        float p0 = h0.x * w4.x + h0.y * w4.y + h0.z * w4.z + h0.w * w4.w;
        float p1 = h1.x * w4.x + h1.y * w4.y + h1.z * w4.z + h1.w * w4.w;
        float p2 = h2.x * w4.x + h2.y * w4.y + h2.z * w4.z + h2.w * w4.w;
        float p3 = h3.x * w4.x + h3.y * w4.y + h3.z * w4.z + h3.w * w4.w;

        // four independent butterfly chains — latencies overlap
        #pragma unroll
        for (int m = 16; m >= 1; m >>= 1) {
            p0 += __shfl_xor_sync(0xFFFFFFFFu, p0, m);
            p1 += __shfl_xor_sync(0xFFFFFFFFu, p1, m);
            p2 += __shfl_xor_sync(0xFFFFFFFFu, p2, m);
            p3 += __shfl_xor_sync(0xFFFFFFFFu, p3, m);
        }

        float l0 = __expf(p0 + bias);
        float l1 = __expf(p1 + bias);
        float l2 = __expf(p2 + bias);
        float l3 = __expf(p3 + bias);

        ACCUM(bv.x, h0, l0);
        ACCUM(bv.y, h1, l1);
        ACCUM(bv.z, h2, l2);
        ACCUM(bv.w, h3, l3);
    }

    // tail
    for (; r < end; ++r) {
        int s = batch[r];
        float4 h = reinterpret_cast<const float4*>(H + r * DCOLS)[lane];
        float p = h.x * w4.x + h.y * w4.y + h.z * w4.z + h.w * w4.w;
        p = warp_bcast_sum(p);
        float l = __expf(p + bias);
        ACCUM(s, h, l);
    }

    FLUSH();
#undef ACCUM
#undef FLUSH
}

__global__ void div_kernel(float* out, int n_out) {
    int i = blockIdx.x * blockDim.x + threadIdx.x;
    if (i < n_out) {
        float z = g_Z[i >> 7];  // i / 128 -> graph id
        out[i] = (z > 0.f) ? out[i] / z : 0.f;
    }
}

extern "C" void kernel_launch(void* const* d_in, const int* in_sizes, int n_in,
                              void* d_out, int out_size) {
    const float* H     = (const float*)d_in[0];
    const int*   batch = (const int*)d_in[1];
    const float* w     = (const float*)d_in[2];
    const float* b     = (const float*)d_in[3];
    float*       out   = (float*)d_out;

    int V  = in_sizes[1];           // number of rows
    int ng = out_size / DCOLS;      // number of graphs

    {
        int n = out_size > ng ? out_size : ng;
        int threads = 256;
        int blocks = (n + threads - 1) / threads;
        zero_kernel<<<blocks, threads>>>(out, out_size, ng);
    }
    {
        const int rows_per_warp = 128;
        long warps = ((long)V + rows_per_warp - 1) / rows_per_warp;
        int threads = 256;
        long blocks = (warps * 32 + threads - 1) / threads;
        agg_kernel<<<(int)blocks, threads>>>(H, batch, w, b, out, V, rows_per_warp);
    }
    {
        int threads = 256;
        int blocks = (out_size + threads - 1) / threads;
        div_kernel<<<blocks, threads>>>(out, out_size);
    }
}